// round 1
// baseline (speedup 1.0000x reference)
#include <cuda_runtime.h>
#include <cuda_bf16.h>

#define GS_FX 500.0f
#define GS_FY 500.0f

__device__ __forceinline__ float clipf(float v, float lo, float hi) {
    return fminf(fmaxf(v, lo), hi);
}

__device__ __forceinline__ void gs_one(
    float px, float py, float pz, float sx_in, float sy_in, float o,
    float r00, float r01, float r02, float tx,
    float r10, float r11, float r12, float ty,
    float r20, float r21, float r22, float tz,
    float hw, float hh, float xmax, float ymax,
    float& xo, float& yo, float& zo, float& c00, float& c11,
    float& op_out, float& valid)
{
    float ax = px - tx, ay = py - ty, az = pz - tz;
    float vx = clipf(fmaf(r00, ax, fmaf(r01, ay, r02 * az)), -100.0f, 100.0f);
    float vy = clipf(fmaf(r10, ax, fmaf(r11, ay, r12 * az)), -100.0f, 100.0f);
    float vz = clipf(fmaf(r20, ax, fmaf(r21, ay, r22 * az)), -100.0f, 100.0f);

    valid = (vz > 0.1f && vz < 10.0f) ? 1.0f : 0.0f;

    float z   = clipf(vz, 0.1f, 10.0f);
    float inv = __fdividef(GS_FX, z);   // FX == FY

    xo = clipf(fmaf(vx, inv, hw), -1000.0f, xmax);
    yo = clipf(fmaf(-vy, inv, hh), -1000.0f, ymax);
    zo = vz;

    float ssx = fmaxf(sx_in, 0.001f) * inv;
    float ssy = fmaxf(sy_in, 0.001f) * inv;
    c00 = clipf(fmaf(ssx, ssx, 1e-4f), 1e-6f, 1e6f);
    c11 = clipf(fmaf(ssy, ssy, 1e-4f), 1e-6f, 1e6f);

    op_out = __fdividef(1.0f, 1.0f + __expf(-o));
}

// Vectorized path: 4 Gaussians per thread, all 128-bit memory ops. Requires N % 4 == 0.
__global__ void __launch_bounds__(256)
gs_vec_kernel(const float4* __restrict__ pos4,
              const float4* __restrict__ sc4,
              const float4* __restrict__ col4,
              const float4* __restrict__ op4,
              const float*  __restrict__ vm,
              const int*    __restrict__ wp,
              const int*    __restrict__ hp,
              float* __restrict__ out, int N)
{
    int g = blockIdx.x * blockDim.x + threadIdx.x;
    int G = N >> 2;
    if (g >= G) return;

    float r00 = vm[0], r01 = vm[1],  r02 = vm[2],  tx = vm[3];
    float r10 = vm[4], r11 = vm[5],  r12 = vm[6],  ty = vm[7];
    float r20 = vm[8], r21 = vm[9],  r22 = vm[10], tz = vm[11];
    float W = (float)(*wp), H = (float)(*hp);
    float hw = W * 0.5f, hh = H * 0.5f;
    float xmax = W + 1000.0f, ymax = H + 1000.0f;

    // 3 float4 = 4 gaussians x 3 components
    float4 p0 = pos4[3 * g], p1 = pos4[3 * g + 1], p2 = pos4[3 * g + 2];
    float4 s0 = sc4[3 * g],  s1 = sc4[3 * g + 1],  s2 = sc4[3 * g + 2];
    float4 c0 = col4[3 * g], c1 = col4[3 * g + 1], c2 = col4[3 * g + 2];
    float4 o4 = op4[g];

    float px[4] = {p0.x, p0.w, p1.z, p2.y};
    float py[4] = {p0.y, p1.x, p1.w, p2.z};
    float pz[4] = {p0.z, p1.y, p2.x, p2.w};
    float sx[4] = {s0.x, s0.w, s1.z, s2.y};
    float sy[4] = {s0.y, s1.x, s1.w, s2.z};
    float oa[4] = {o4.x, o4.y, o4.z, o4.w};

    float xs[4], ys[4], zs[4], c00[4], c11[4], oo[4], vf[4];
#pragma unroll
    for (int j = 0; j < 4; j++) {
        gs_one(px[j], py[j], pz[j], sx[j], sy[j], oa[j],
               r00, r01, r02, tx, r10, r11, r12, ty, r20, r21, r22, tz,
               hw, hh, xmax, ymax,
               xs[j], ys[j], zs[j], c00[j], c11[j], oo[j], vf[j]);
    }

    float4* o4p = (float4*)out;

    // proj_points: floats [0, 3N) -> float4 [0, 3G)
    o4p[3 * g + 0] = make_float4(xs[0], ys[0], zs[0], xs[1]);
    o4p[3 * g + 1] = make_float4(ys[1], zs[1], xs[2], ys[2]);
    o4p[3 * g + 2] = make_float4(zs[2], xs[3], ys[3], zs[3]);

    // cov2d: floats [3N, 7N) -> one float4 per gaussian
    long cb = 3L * G;
#pragma unroll
    for (int j = 0; j < 4; j++)
        o4p[cb + 4L * g + j] = make_float4(c00[j], 1e-6f, 1e-6f, c11[j]);

    // colors: floats [7N, 10N)
    long kb = 7L * G;
    o4p[kb + 3 * g + 0] = make_float4(clipf(c0.x,0.f,1.f), clipf(c0.y,0.f,1.f), clipf(c0.z,0.f,1.f), clipf(c0.w,0.f,1.f));
    o4p[kb + 3 * g + 1] = make_float4(clipf(c1.x,0.f,1.f), clipf(c1.y,0.f,1.f), clipf(c1.z,0.f,1.f), clipf(c1.w,0.f,1.f));
    o4p[kb + 3 * g + 2] = make_float4(clipf(c2.x,0.f,1.f), clipf(c2.y,0.f,1.f), clipf(c2.z,0.f,1.f), clipf(c2.w,0.f,1.f));

    // opacities: floats [10N, 11N)
    o4p[10L * G + g] = make_float4(oo[0], oo[1], oo[2], oo[3]);

    // valid mask: floats [11N, 12N)
    o4p[11L * G + g] = make_float4(vf[0], vf[1], vf[2], vf[3]);
}

// Scalar fallback for N % 4 != 0 (not expected with N = 4,000,000).
__global__ void __launch_bounds__(256)
gs_scalar_kernel(const float* __restrict__ pos,
                 const float* __restrict__ sc,
                 const float* __restrict__ col,
                 const float* __restrict__ op,
                 const float* __restrict__ vm,
                 const int*   __restrict__ wp,
                 const int*   __restrict__ hp,
                 float* __restrict__ out, int N)
{
    int i = blockIdx.x * blockDim.x + threadIdx.x;
    if (i >= N) return;

    float r00 = vm[0], r01 = vm[1],  r02 = vm[2],  tx = vm[3];
    float r10 = vm[4], r11 = vm[5],  r12 = vm[6],  ty = vm[7];
    float r20 = vm[8], r21 = vm[9],  r22 = vm[10], tz = vm[11];
    float W = (float)(*wp), H = (float)(*hp);
    float hw = W * 0.5f, hh = H * 0.5f;
    float xmax = W + 1000.0f, ymax = H + 1000.0f;

    float xo, yo, zo, c00, c11, oo, vf;
    gs_one(pos[3*i], pos[3*i+1], pos[3*i+2], sc[3*i], sc[3*i+1], op[i],
           r00, r01, r02, tx, r10, r11, r12, ty, r20, r21, r22, tz,
           hw, hh, xmax, ymax, xo, yo, zo, c00, c11, oo, vf);

    long n = N;
    out[3*i+0] = xo; out[3*i+1] = yo; out[3*i+2] = zo;
    out[3*n + 4L*i + 0] = c00;
    out[3*n + 4L*i + 1] = 1e-6f;
    out[3*n + 4L*i + 2] = 1e-6f;
    out[3*n + 4L*i + 3] = c11;
    out[7*n + 3L*i + 0] = clipf(col[3*i+0], 0.f, 1.f);
    out[7*n + 3L*i + 1] = clipf(col[3*i+1], 0.f, 1.f);
    out[7*n + 3L*i + 2] = clipf(col[3*i+2], 0.f, 1.f);
    out[10*n + i] = oo;
    out[11*n + i] = vf;
}

extern "C" void kernel_launch(void* const* d_in, const int* in_sizes, int n_in,
                              void* d_out, int out_size)
{
    const float* positions = (const float*)d_in[0];
    const float* scales    = (const float*)d_in[1];
    // d_in[2] rotations: unused by the reference math
    const float* colors    = (const float*)d_in[3];
    const float* opac      = (const float*)d_in[4];
    const float* viewmat   = (const float*)d_in[5];
    // d_in[6] projmat: unused
    const int*   wp        = (const int*)d_in[7];
    const int*   hp        = (const int*)d_in[8];
    float* out = (float*)d_out;

    int N = in_sizes[0] / 3;

    if ((N & 3) == 0) {
        int G = N >> 2;
        int threads = 256;
        int blocks = (G + threads - 1) / threads;
        gs_vec_kernel<<<blocks, threads>>>(
            (const float4*)positions, (const float4*)scales,
            (const float4*)colors, (const float4*)opac,
            viewmat, wp, hp, out, N);
    } else {
        int threads = 256;
        int blocks = (N + threads - 1) / threads;
        gs_scalar_kernel<<<blocks, threads>>>(
            positions, scales, colors, opac, viewmat, wp, hp, out, N);
    }
}